// round 12
// baseline (speedup 1.0000x reference)
#include <cuda_runtime.h>
#include <cuda_fp16.h>
#include <cstdint>

// out = elu(input @ W)  [reference's softmax(eye-mask) == Identity exactly]
// fp32 GEMM M=8192 N=2048 K=2048, single fp16 term on mma.sync.m16n8k16
// (measured rel_err 3.0e-4 < 1e-3).
// R11: ncu showed tensor=62.3% ~= L1=62.2% (co-saturated). Cut smem traffic:
//   CTA 128x128 with FOUR warps (128 thr), warp tile 64x64 (128 acc regs/thr,
//   fits RF at occ-2 since only 128 thr/CTA), 3-stage ring, occ-2.
//   smem/chunk 128KB->96KB (A redundancy 4->2), MMA:ldsm 2.67->4:1.
//   2 warps/SMSP but split across two async CTAs (decorrelated stalls — the
//   R9 lesson), unlike R7's correlated single-CTA 2/SMSP.

#define GM 8192
#define GN 2048
#define GK 2048

#define BM 128
#define BN 128
#define BK 64
#define NTHREADS 128
#define NCHUNK (GK / BK)   // 32

// ---------------- scratch (fp16 operands) ----------------
__device__ __half g_Ah[(size_t)GM * GK];
__device__ __half g_Bh[(size_t)GN * GK];   // W^T, K-major rows

// ---------------- smem stage layout ----------------
// per stage: Ah 16K | Bh 16K   (rows of 128B, SW128)
#define SA 0
#define SB 16384
#define STAGE_BYTES 32768
#define NSTAGE 3
#define SMEM_TOTAL (NSTAGE * STAGE_BYTES)   // 98304/CTA; x2 CTAs = 192KB/SM

#define SWZ(o) ((o) ^ (((o) >> 3) & 0x70))

__device__ __forceinline__ uint32_t smem_u32(const void* p) {
    uint32_t a;
    asm("{ .reg .u64 t; cvta.to.shared.u64 t, %1; cvt.u32.u64 %0, t; }" : "=r"(a) : "l"(p));
    return a;
}
__device__ __forceinline__ void cp16(uint32_t dst, const void* src) {
    asm volatile("cp.async.cg.shared.global [%0], [%1], 16;" :: "r"(dst), "l"(src));
}
__device__ __forceinline__ void cp_commit() {
    asm volatile("cp.async.commit_group;" ::: "memory");
}
__device__ __forceinline__ void cp_wait1() {
    asm volatile("cp.async.wait_group 1;" ::: "memory");
}
__device__ __forceinline__ void ldsm4(uint32_t addr, uint32_t& r0, uint32_t& r1,
                                      uint32_t& r2, uint32_t& r3) {
    asm volatile("ldmatrix.sync.aligned.m8n8.x4.shared.b16 {%0,%1,%2,%3}, [%4];"
                 : "=r"(r0), "=r"(r1), "=r"(r2), "=r"(r3) : "r"(addr));
}
__device__ __forceinline__ void mma16816(float& d0, float& d1, float& d2, float& d3,
                                         uint32_t a0, uint32_t a1, uint32_t a2, uint32_t a3,
                                         uint32_t b0, uint32_t b1) {
    asm volatile(
        "mma.sync.aligned.m16n8k16.row.col.f32.f16.f16.f32 "
        "{%0,%1,%2,%3}, {%4,%5,%6,%7}, {%8,%9}, {%0,%1,%2,%3};"
        : "+f"(d0), "+f"(d1), "+f"(d2), "+f"(d3)
        : "r"(a0), "r"(a1), "r"(a2), "r"(a3), "r"(b0), "r"(b1));
}
__device__ __forceinline__ float elu_f(float x) { return x > 0.0f ? x : expm1f(x); }

// ---------------- merged conversion kernel ----------------
// blocks [0, 4096): A fp32 -> fp16 (16 floats per thread)
// blocks [4096, 8192): W fp32 -> W^T fp16 via smem transpose (32x32 tile)
#define CONV_A_BLOCKS 4096
__global__ __launch_bounds__(256) void conv_kernel(const float* __restrict__ A,
                                                   const float* __restrict__ B) {
    __shared__ float tile[32][33];
    int bid = blockIdx.x;
    int tid = threadIdx.x;
    if (bid < CONV_A_BLOCKS) {
        const float4* A4 = reinterpret_cast<const float4*>(A);
        size_t base = (size_t)bid * 1024 + tid;
        #pragma unroll
        for (int i = 0; i < 4; i++) {
            size_t idx = base + (size_t)i * 256;
            float4 v = A4[idx];
            __half2* ph = reinterpret_cast<__half2*>(g_Ah + idx * 4);
            ph[0] = __half2(__float2half(v.x), __float2half(v.y));
            ph[1] = __half2(__float2half(v.z), __float2half(v.w));
        }
    } else {
        int b = bid - CONV_A_BLOCKS;          // 0..4095
        int n0 = (b & 63) * 32;               // 64 n-tiles
        int k0 = (b >> 6) * 32;               // 64 k-tiles
        int tx = tid & 31, ty = tid >> 5;     // (32,8) logical
        #pragma unroll
        for (int j = 0; j < 32; j += 8)
            tile[ty + j][tx] = B[(size_t)(k0 + ty + j) * GN + n0 + tx];
        __syncthreads();
        #pragma unroll
        for (int j = 0; j < 32; j += 8) {
            float x = tile[tx][ty + j];
            g_Bh[(size_t)(n0 + ty + j) * GK + k0 + tx] = __float2half(x);
        }
    }
}

// ---------------- stage fill (one BK=64 chunk) ----------------
__device__ __forceinline__ void fill_stage(uint32_t sbase, int m0, int n0, int k0) {
    const int tid = threadIdx.x;
    const char* Ah = (const char*)g_Ah;
    const char* Bh = (const char*)g_Bh;
    // A tile: 128 rows x 128B  (1024 cp16, 8 per thread)
    #pragma unroll
    for (int i = tid; i < 1024; i += NTHREADS) {
        int r = i >> 3, c = i & 7;
        uint32_t off = SWZ((uint32_t)(r * 128 + c * 16));
        size_t go = ((size_t)(m0 + r) * GK + k0) * 2 + c * 16;
        cp16(sbase + SA + off, Ah + go);
    }
    // B tile: 128 rows x 128B  (1024 cp16, 8 per thread)
    #pragma unroll
    for (int i = tid; i < 1024; i += NTHREADS) {
        int r = i >> 3, c = i & 7;
        uint32_t off = SWZ((uint32_t)(r * 128 + c * 16));
        size_t go = ((size_t)(n0 + r) * GK + k0) * 2 + c * 16;
        cp16(sbase + SB + off, Bh + go);
    }
}

// ---------------- main GEMM kernel ----------------
__global__ __launch_bounds__(NTHREADS, 2)
void gat_mma_kernel(float* __restrict__ C) {
    extern __shared__ char smem[];
    uint32_t sb = smem_u32(smem);
    const int tid  = threadIdx.x;
    const int wid  = tid >> 5;
    const int lane = tid & 31;
    const int m0 = blockIdx.y * BM;
    const int n0 = blockIdx.x * BN;
    const int warp_m = wid & 1;    // 2 M-tiles of 64
    const int warp_n = wid >> 1;   // 2 N-tiles of 64

    float acc[4][8][4];
    #pragma unroll
    for (int i = 0; i < 4; i++)
        #pragma unroll
        for (int j = 0; j < 8; j++)
            #pragma unroll
            for (int t = 0; t < 4; t++) acc[i][j][t] = 0.0f;

    // per-lane swizzled address bases:
    // SWZ(row*128 + c) == row*128 + (c ^ ((row&7)<<4))  for c < 128
    const int a_row_l = lane & 15;
    const uint32_t a_kb = (uint32_t)((lane >> 4) << 4);
    const int b_j = lane >> 3;
    const int b_row_l = (lane & 7) + ((b_j >> 1) << 3);
    const uint32_t b_kb = (uint32_t)((b_j & 1) << 4);

    uint32_t baseA[4], xA[4];
    #pragma unroll
    for (int mt = 0; mt < 4; mt++) {
        int row = warp_m * 64 + mt * 16 + a_row_l;
        baseA[mt] = (uint32_t)(row << 7);
        xA[mt]    = (uint32_t)((row & 7) << 4);
    }
    uint32_t baseB[4], xB[4];
    #pragma unroll
    for (int np = 0; np < 4; np++) {
        int row = warp_n * 64 + np * 16 + b_row_l;
        baseB[np] = (uint32_t)(row << 7);
        xB[np]    = (uint32_t)((row & 7) << 4);
    }

    // prologue: fill 3 stages (chunks 0,1,2), one commit group each
    #pragma unroll
    for (int s = 0; s < NSTAGE; s++) {
        fill_stage(sb + (uint32_t)s * STAGE_BYTES, m0, n0, s * BK);
        cp_commit();
    }

    for (int k = 0; k < NCHUNK; k++) {
        cp_wait1();        // chunk k resident (<=1 newer group in flight)
        __syncthreads();   // all warps done reading chunk k-1; writes visible

        // refill slot of chunk k-1 with chunk k+2 (safe: barrier above proves
        // all warps finished last iteration's reads of that slot)
        if (k >= 1) {
            int kc = k + 2;
            if (kc < NCHUNK) {
                uint32_t rs = sb + (uint32_t)(kc % NSTAGE) * STAGE_BYTES;
                fill_stage(rs, m0, n0, kc * BK);
            }
            cp_commit();   // empty group when kc >= NCHUNK keeps accounting
        }

        uint32_t stage = sb + (uint32_t)(k % NSTAGE) * STAGE_BYTES;
        #pragma unroll
        for (int ks = 0; ks < 4; ks++) {
            const uint32_t kb = (uint32_t)(ks * 32);

            // B fragments: 4 ldsm.x4 cover 8 n-tiles (warp's 64 cols)
            uint32_t bh[8][2];
            #pragma unroll
            for (int np = 0; np < 4; np++) {
                uint32_t ad = stage + SB + baseB[np] + ((kb + b_kb) ^ xB[np]);
                uint32_t r0, r1, r2, r3;
                ldsm4(ad, r0, r1, r2, r3);
                bh[np * 2 + 0][0] = r0; bh[np * 2 + 0][1] = r1;
                bh[np * 2 + 1][0] = r2; bh[np * 2 + 1][1] = r3;
            }

            // A fragments double-buffered over mt; 8 MMAs per mt
            uint32_t ah[2][4];
            {
                uint32_t ad = stage + SA + baseA[0] + ((kb + a_kb) ^ xA[0]);
                ldsm4(ad, ah[0][0], ah[0][1], ah[0][2], ah[0][3]);
            }
            #pragma unroll
            for (int mt = 0; mt < 4; mt++) {
                const int cb = mt & 1;
                if (mt < 3) {
                    const int nb = (mt + 1) & 1;
                    uint32_t ad = stage + SA + baseA[mt + 1] + ((kb + a_kb) ^ xA[mt + 1]);
                    ldsm4(ad, ah[nb][0], ah[nb][1], ah[nb][2], ah[nb][3]);
                }
                #pragma unroll
                for (int nt = 0; nt < 8; nt++)
                    mma16816(acc[mt][nt][0], acc[mt][nt][1], acc[mt][nt][2], acc[mt][nt][3],
                             ah[cb][0], ah[cb][1], ah[cb][2], ah[cb][3],
                             bh[nt][0], bh[nt][1]);
            }
        }
    }

    // ---------------- epilogue: fused elu, float2 stores ----------------
    const int gp  = lane >> 2;
    const int tg2 = (lane & 3) * 2;
    #pragma unroll
    for (int mt = 0; mt < 4; mt++) {
        int mrow = m0 + warp_m * 64 + mt * 16 + gp;
        #pragma unroll
        for (int nt = 0; nt < 8; nt++) {
            int ncol = n0 + warp_n * 64 + nt * 8 + tg2;
            float2 v0, v1;
            v0.x = elu_f(acc[mt][nt][0]);
            v0.y = elu_f(acc[mt][nt][1]);
            v1.x = elu_f(acc[mt][nt][2]);
            v1.y = elu_f(acc[mt][nt][3]);
            *reinterpret_cast<float2*>(C + (size_t)mrow * GN + ncol) = v0;
            *reinterpret_cast<float2*>(C + (size_t)(mrow + 8) * GN + ncol) = v1;
        }
    }
}

// ---------------- launch ----------------
extern "C" void kernel_launch(void* const* d_in, const int* in_sizes, int n_in,
                              void* d_out, int out_size) {
    const float* input = (const float*)d_in[0];   // [8192, 2048]
    const float* W     = (const float*)d_in[2];   // [2048, 2048]
    float*       out   = (float*)d_out;

    cudaFuncSetAttribute(gat_mma_kernel,
                         cudaFuncAttributeMaxDynamicSharedMemorySize, SMEM_TOTAL);

    conv_kernel<<<CONV_A_BLOCKS + 4096, 256>>>(input, W);
    gat_mma_kernel<<<dim3(GN / BN, GM / BM), NTHREADS, SMEM_TOTAL>>>(out);
}

// round 13
// speedup vs baseline: 1.1280x; 1.1280x over previous
#include <cuda_runtime.h>
#include <cuda_fp16.h>
#include <cstdint>

// out = elu(input @ W)  [reference's softmax(eye-mask) == Identity exactly]
// fp32 GEMM M=8192 N=2048 K=2048, single fp16 term on mma.sync.m16n8k16
// (measured rel_err 3.0e-4 < 1e-3).
// R12: R10 config restored (occ-2, 2x 8-warp CTAs = 16 warps/SM — hard
//   requirement per R7/R9/R11; warp 64x32; 3-stage ring; 1 sync/chunk).
//   NEW: fill_stage address math hoisted. With 256 threads over 1024 items,
//   c=tid&7 is constant and r steps by 32 (≡0 mod 8) so the SW128 mask is
//   invariant: one per-thread smem offset s0 (same for A and B) + immediate
//   j*4096 offsets + two persistent global pointers stepped by kc*128.
//   Per-chunk fill ALU ~60 ops -> ~4. Stage ring via rotating pointers.

#define GM 8192
#define GN 2048
#define GK 2048

#define BM 128
#define BN 128
#define BK 64
#define NTHREADS 256
#define NCHUNK (GK / BK)   // 32

// ---------------- scratch (fp16 operands) ----------------
__device__ __half g_Ah[(size_t)GM * GK];
__device__ __half g_Bh[(size_t)GN * GK];   // W^T, K-major rows

// ---------------- smem stage layout ----------------
// per stage: Ah 16K | Bh 16K   (rows of 128B, SW128)
#define SA 0
#define SB 16384
#define STAGE_BYTES 32768
#define NSTAGE 3
#define SMEM_TOTAL (NSTAGE * STAGE_BYTES)   // 98304/CTA; x2 CTAs = 192KB/SM

#define SWZ(o) ((o) ^ (((o) >> 3) & 0x70))

__device__ __forceinline__ uint32_t smem_u32(const void* p) {
    uint32_t a;
    asm("{ .reg .u64 t; cvta.to.shared.u64 t, %1; cvt.u32.u64 %0, t; }" : "=r"(a) : "l"(p));
    return a;
}
__device__ __forceinline__ void cp16(uint32_t dst, const void* src) {
    asm volatile("cp.async.cg.shared.global [%0], [%1], 16;" :: "r"(dst), "l"(src));
}
__device__ __forceinline__ void cp_commit() {
    asm volatile("cp.async.commit_group;" ::: "memory");
}
__device__ __forceinline__ void cp_wait1() {
    asm volatile("cp.async.wait_group 1;" ::: "memory");
}
__device__ __forceinline__ void ldsm4(uint32_t addr, uint32_t& r0, uint32_t& r1,
                                      uint32_t& r2, uint32_t& r3) {
    asm volatile("ldmatrix.sync.aligned.m8n8.x4.shared.b16 {%0,%1,%2,%3}, [%4];"
                 : "=r"(r0), "=r"(r1), "=r"(r2), "=r"(r3) : "r"(addr));
}
__device__ __forceinline__ void mma16816(float& d0, float& d1, float& d2, float& d3,
                                         uint32_t a0, uint32_t a1, uint32_t a2, uint32_t a3,
                                         uint32_t b0, uint32_t b1) {
    asm volatile(
        "mma.sync.aligned.m16n8k16.row.col.f32.f16.f16.f32 "
        "{%0,%1,%2,%3}, {%4,%5,%6,%7}, {%8,%9}, {%0,%1,%2,%3};"
        : "+f"(d0), "+f"(d1), "+f"(d2), "+f"(d3)
        : "r"(a0), "r"(a1), "r"(a2), "r"(a3), "r"(b0), "r"(b1));
}
__device__ __forceinline__ float elu_f(float x) { return x > 0.0f ? x : expm1f(x); }

// ---------------- merged conversion kernel ----------------
#define CONV_A_BLOCKS 4096
__global__ __launch_bounds__(256) void conv_kernel(const float* __restrict__ A,
                                                   const float* __restrict__ B) {
    __shared__ float tile[32][33];
    int bid = blockIdx.x;
    int tid = threadIdx.x;
    if (bid < CONV_A_BLOCKS) {
        const float4* A4 = reinterpret_cast<const float4*>(A);
        size_t base = (size_t)bid * 1024 + tid;
        #pragma unroll
        for (int i = 0; i < 4; i++) {
            size_t idx = base + (size_t)i * 256;
            float4 v = A4[idx];
            __half2* ph = reinterpret_cast<__half2*>(g_Ah + idx * 4);
            ph[0] = __half2(__float2half(v.x), __float2half(v.y));
            ph[1] = __half2(__float2half(v.z), __float2half(v.w));
        }
    } else {
        int b = bid - CONV_A_BLOCKS;          // 0..4095
        int n0 = (b & 63) * 32;
        int k0 = (b >> 6) * 32;
        int tx = tid & 31, ty = tid >> 5;
        #pragma unroll
        for (int j = 0; j < 32; j += 8)
            tile[ty + j][tx] = B[(size_t)(k0 + ty + j) * GN + n0 + tx];
        __syncthreads();
        #pragma unroll
        for (int j = 0; j < 32; j += 8) {
            float x = tile[tx][ty + j];
            g_Bh[(size_t)(n0 + ty + j) * GK + k0 + tx] = __float2half(x);
        }
    }
}

// ---------------- hoisted stage fill (one BK=64 chunk) ----------------
// s0: per-thread swizzled smem offset (identical for A and B tiles).
// pA/pB: per-thread global base pointers (chunk 0). kc*128 = chunk byte step.
__device__ __forceinline__ void fill_stage2(uint32_t sbase, uint32_t s0,
                                            const char* pA, const char* pB,
                                            int kc) {
    const size_t koff = (size_t)kc * 128;
    #pragma unroll
    for (int j = 0; j < 4; j++) {
        cp16(sbase + SA + s0 + j * 4096, pA + koff + (size_t)j * 131072);
        cp16(sbase + SB + s0 + j * 4096, pB + koff + (size_t)j * 131072);
    }
}

// ---------------- main GEMM kernel ----------------
__global__ __launch_bounds__(NTHREADS, 2)
void gat_mma_kernel(float* __restrict__ C) {
    extern __shared__ char smem[];
    uint32_t sb = smem_u32(smem);
    const int tid  = threadIdx.x;
    const int wid  = tid >> 5;
    const int lane = tid & 31;
    const int m0 = blockIdx.y * BM;
    const int n0 = blockIdx.x * BN;
    const int warp_m = wid & 1;    // 2 M-tiles of 64
    const int warp_n = wid >> 1;   // 4 N-tiles of 32

    // per-thread fill addressing (hoisted; see header comment)
    const uint32_t s0 = (uint32_t)((tid >> 3) * 128 +
                        (((tid & 7) * 16) ^ (((tid >> 3) & 7) << 4)));
    const char* pA = (const char*)g_Ah + (size_t)(m0 + (tid >> 3)) * 4096 + (tid & 7) * 16;
    const char* pB = (const char*)g_Bh + (size_t)(n0 + (tid >> 3)) * 4096 + (tid & 7) * 16;

    float acc[4][4][4];
    #pragma unroll
    for (int i = 0; i < 4; i++)
        #pragma unroll
        for (int j = 0; j < 4; j++)
            #pragma unroll
            for (int t = 0; t < 4; t++) acc[i][j][t] = 0.0f;

    // per-lane swizzled ldsm bases:
    // SWZ(row*128 + c) == row*128 + (c ^ ((row&7)<<4))  for c < 128
    const int a_row_l = lane & 15;
    const uint32_t a_kb = (uint32_t)((lane >> 4) << 4);
    const int b_j = lane >> 3;
    const int b_row_l = (lane & 7) + ((b_j >> 1) << 3);
    const uint32_t b_kb = (uint32_t)((b_j & 1) << 4);

    uint32_t baseA[4], xA[4];
    #pragma unroll
    for (int mt = 0; mt < 4; mt++) {
        int row = warp_m * 64 + mt * 16 + a_row_l;
        baseA[mt] = (uint32_t)(row << 7);
        xA[mt]    = (uint32_t)((row & 7) << 4);
    }
    uint32_t baseB[2], xB[2];
    #pragma unroll
    for (int np = 0; np < 2; np++) {
        int row = warp_n * 32 + np * 16 + b_row_l;
        baseB[np] = (uint32_t)(row << 7);
        xB[np]    = (uint32_t)((row & 7) << 4);
    }

    // prologue: fill 3 stages (chunks 0,1,2)
    #pragma unroll
    for (int s = 0; s < NSTAGE; s++) {
        fill_stage2(sb + (uint32_t)s * STAGE_BYTES, s0, pA, pB, s);
        cp_commit();
    }

    uint32_t stage = sb;                 // stage of chunk k
    uint32_t prev  = sb + 2 * STAGE_BYTES;  // stage of chunk k-1 (dummy at k=0)
    const uint32_t ring_end = sb + NSTAGE * STAGE_BYTES;

    for (int k = 0; k < NCHUNK; k++) {
        cp_wait1();        // chunk k resident (<=1 newer group in flight)
        __syncthreads();   // all warps done reading chunk k-1; writes visible

        // refill chunk k-1's slot with chunk k+2
        if (k >= 1) {
            int kc = k + 2;
            if (kc < NCHUNK) fill_stage2(prev, s0, pA, pB, kc);
            cp_commit();   // empty group when kc >= NCHUNK keeps accounting
        }

        #pragma unroll
        for (int ks = 0; ks < 4; ks++) {
            const uint32_t kb = (uint32_t)(ks * 32);

            // B fragments: 2 ldsm.x4 cover 4 n-tiles (warp's 32 cols)
            uint32_t bh[4][2];
            #pragma unroll
            for (int np = 0; np < 2; np++) {
                uint32_t ad = stage + SB + baseB[np] + ((kb + b_kb) ^ xB[np]);
                uint32_t r0, r1, r2, r3;
                ldsm4(ad, r0, r1, r2, r3);
                bh[np * 2 + 0][0] = r0; bh[np * 2 + 0][1] = r1;
                bh[np * 2 + 1][0] = r2; bh[np * 2 + 1][1] = r3;
            }

            // A fragments double-buffered over mt; 4 MMAs per mt
            uint32_t ah[2][4];
            {
                uint32_t ad = stage + SA + baseA[0] + ((kb + a_kb) ^ xA[0]);
                ldsm4(ad, ah[0][0], ah[0][1], ah[0][2], ah[0][3]);
            }
            #pragma unroll
            for (int mt = 0; mt < 4; mt++) {
                const int cb = mt & 1;
                if (mt < 3) {
                    const int nb = (mt + 1) & 1;
                    uint32_t ad = stage + SA + baseA[mt + 1] + ((kb + a_kb) ^ xA[mt + 1]);
                    ldsm4(ad, ah[nb][0], ah[nb][1], ah[nb][2], ah[nb][3]);
                }
                #pragma unroll
                for (int nt = 0; nt < 4; nt++)
                    mma16816(acc[mt][nt][0], acc[mt][nt][1], acc[mt][nt][2], acc[mt][nt][3],
                             ah[cb][0], ah[cb][1], ah[cb][2], ah[cb][3],
                             bh[nt][0], bh[nt][1]);
            }
        }

        prev = stage;
        stage += STAGE_BYTES;
        if (stage == ring_end) stage = sb;
    }

    // ---------------- epilogue: fused elu, float2 stores ----------------
    const int gp  = lane >> 2;
    const int tg2 = (lane & 3) * 2;
    #pragma unroll
    for (int mt = 0; mt < 4; mt++) {
        int mrow = m0 + warp_m * 64 + mt * 16 + gp;
        #pragma unroll
        for (int nt = 0; nt < 4; nt++) {
            int ncol = n0 + warp_n * 32 + nt * 8 + tg2;
            float2 v0, v1;
            v0.x = elu_f(acc[mt][nt][0]);
            v0.y = elu_f(acc[mt][nt][1]);
            v1.x = elu_f(acc[mt][nt][2]);
            v1.y = elu_f(acc[mt][nt][3]);
            *reinterpret_cast<float2*>(C + (size_t)mrow * GN + ncol) = v0;
            *reinterpret_cast<float2*>(C + (size_t)(mrow + 8) * GN + ncol) = v1;
        }
    }
}

// ---------------- launch ----------------
extern "C" void kernel_launch(void* const* d_in, const int* in_sizes, int n_in,
                              void* d_out, int out_size) {
    const float* input = (const float*)d_in[0];   // [8192, 2048]
    const float* W     = (const float*)d_in[2];   // [2048, 2048]
    float*       out   = (float*)d_out;

    cudaFuncSetAttribute(gat_mma_kernel,
                         cudaFuncAttributeMaxDynamicSharedMemorySize, SMEM_TOTAL);

    conv_kernel<<<CONV_A_BLOCKS + 4096, 256>>>(input, W);
    gat_mma_kernel<<<dim3(GN / BN, GM / BM), NTHREADS, SMEM_TOTAL>>>(out);
}